// round 16
// baseline (speedup 1.0000x reference)
#include <cuda_runtime.h>
#include <cuda_fp16.h>
#include <math.h>
#include <stdint.h>

#define Bc 4
#define C 256
#define Tn 4096
#define LATENT 128
#define NENC 40
#define NDEC 10
#define NT 128

#define STAGE_BYTES 32768      // A 16K + B 16K (single-matrix chunk)
#define NSTAGE 3
#define SMEM_TOTAL (NSTAGE * STAGE_BYTES)

// ---------------- device scratch ----------------
__device__ __align__(16) unsigned char g_wp1[(size_t)NENC * 2 * 8 * 4 * 16384]; // 40MB
__device__ __align__(16) unsigned char g_wp2[(size_t)NENC * 2 * 4 * 2 * 16384]; // 10MB
__device__ __align__(16) float  g_hf  [(size_t)Bc * Tn * C];
__device__ __align__(16) __half g_hbf [(size_t)Bc * Tn * C];
__device__ __align__(16) __half g_gbf [(size_t)Bc * Tn * C];
__device__ float g_part[(size_t)NENC * Bc * 32 * C];
__device__ float g_m[NENC * Bc * C];
__device__ float g_pooled[Bc * C];
__device__ float g_z[Bc * LATENT];
__device__ float g_dwfT[NDEC * C * C], g_dwgT[NDEC * C * C], g_dwrT[NDEC * C * C];
__device__ float g_dinT[LATENT * C];
__device__ float g_fmuT[C * LATENT], g_flvT[C * LATENT];

// ---------------- helpers ----------------
__device__ __forceinline__ uint32_t smem_u32(const void* p) {
    uint32_t a;
    asm("{ .reg .u64 t; cvta.to.shared.u64 t, %1; cvt.u32.u64 %0, t; }" : "=r"(a) : "l"(p));
    return a;
}
__device__ __forceinline__ uint32_t swz(uint32_t off) { return off ^ ((off >> 3) & 0x70); }
__device__ __forceinline__ void cp16(uint32_t dst, const void* src, int sz) {
    asm volatile("cp.async.cg.shared.global [%0], [%1], 16, %2;"
                 :: "r"(dst), "l"(src), "r"(sz) : "memory");
}
#define LDSM4(r, addr) \
    asm volatile("ldmatrix.sync.aligned.m8n8.x4.shared.b16 {%0,%1,%2,%3}, [%4];" \
                 : "=r"((r)[0]), "=r"((r)[1]), "=r"((r)[2]), "=r"((r)[3]) : "r"(addr))
#define MMA(c, a, b0r, b1r) \
    asm volatile("mma.sync.aligned.m16n8k16.row.col.f32.f16.f16.f32 " \
                 "{%0,%1,%2,%3}, {%4,%5,%6,%7}, {%8,%9}, {%0,%1,%2,%3};" \
                 : "+f"((c)[0]), "+f"((c)[1]), "+f"((c)[2]), "+f"((c)[3]) \
                 : "r"((a)[0]), "r"((a)[1]), "r"((a)[2]), "r"((a)[3]), "r"(b0r), "r"(b1r))

__device__ __forceinline__ void split2(float v, __half& h, __half& l) {
    h = __float2half(v);
    l = __float2half(v - __half2float(h));
}
__device__ __forceinline__ uint32_t pack2(__half a, __half b) {
    return (uint32_t)__half_as_ushort(a) | ((uint32_t)__half_as_ushort(b) << 16);
}

// ---------------- weight pre-pack: fp16 hi/lo (layouts identical to R12/R14) ----------------
__global__ void prep1_kernel(const float* __restrict__ Wf, const float* __restrict__ Wg) {
    size_t idx = (size_t)blockIdx.x * 256 + threadIdx.x;
    int j2 = idx & 31;
    int r  = (idx >> 5) & 127;
    int kc = (idx >> 12) & 7;
    int oh = (idx >> 15) & 1;
    int l  = (int)(idx >> 16);
    int o = oh * 128 + r;
    int tap = kc >> 2;
    int c = (kc & 3) * 64 + j2 * 2;
    uint32_t boff = swz((uint32_t)(r * 128 + j2 * 4));
    unsigned char* base = g_wp1 + ((((size_t)(l * 2 + oh) * 8 + kc) * 4) << 14) + boff;
    const float* pf = Wf + (((size_t)l * C + o) * C + c) * 2 + tap;
    const float* pg = Wg + (((size_t)l * C + o) * C + c) * 2 + tap;
    __half h0, l0, h1, l1;
    split2(pf[0], h0, l0); split2(pf[2], h1, l1);
    *(uint32_t*)(base)             = pack2(h0, h1);
    *(uint32_t*)(base + 16384)     = pack2(l0, l1);
    split2(pg[0], h0, l0); split2(pg[2], h1, l1);
    *(uint32_t*)(base + 2 * 16384) = pack2(h0, h1);
    *(uint32_t*)(base + 3 * 16384) = pack2(l0, l1);
}
__global__ void prep2_kernel(const float* __restrict__ Wr) {
    size_t idx = (size_t)blockIdx.x * 256 + threadIdx.x;
    int j2 = idx & 31;
    int r  = (idx >> 5) & 127;
    int kc = (idx >> 12) & 3;
    int oh = (idx >> 14) & 1;
    int l  = (int)(idx >> 15);
    int o = oh * 128 + r;
    int c = kc * 64 + j2 * 2;
    uint32_t boff = swz((uint32_t)(r * 128 + j2 * 4));
    unsigned char* base = g_wp2 + ((((size_t)(l * 2 + oh) * 4 + kc) * 2) << 14) + boff;
    const float* pr = Wr + ((size_t)l * C + o) * C + c;
    __half h0, l0, h1, l1;
    split2(pr[0], h0, l0); split2(pr[1], h1, l1);
    *(uint32_t*)(base)         = pack2(h0, h1);
    *(uint32_t*)(base + 16384) = pack2(l0, l1);
}
__global__ void prep3_kernel(const float* __restrict__ dWf, const float* __restrict__ dWg,
                             const float* __restrict__ dWr, const float* __restrict__ dinW,
                             const float* __restrict__ muW, const float* __restrict__ lvW) {
    int idx = blockIdx.x * 256 + threadIdx.x;
    if (idx < NDEC * C * C) {
        int o = idx & 255, cc = (idx >> 8) & 255, l = idx >> 16;
        g_dwfT[idx] = dWf[(((size_t)l * C + o) * C + cc) * 2 + 1];
        g_dwgT[idx] = dWg[(((size_t)l * C + o) * C + cc) * 2 + 1];
        g_dwrT[idx] = dWr[((size_t)l * C + o) * C + cc];
    }
    if (idx < LATENT * C) {
        int o = idx & 255, l = idx >> 8;
        g_dinT[idx] = dinW[o * LATENT + l];
    }
    if (idx < C * LATENT) {
        int l = idx & 127, c = idx >> 7;
        g_fmuT[idx] = muW[l * C + c];
        g_flvT[idx] = lvW[l * C + c];
    }
}

// ---------------- encoder input conv ----------------
__global__ void enc_in_kernel(const float* __restrict__ x,
                              const float* __restrict__ W,
                              const float* __restrict__ bias) {
    size_t idx = (size_t)blockIdx.x * 256 + threadIdx.x;
    int c = idx & 255;
    int t = (int)((idx >> 8) & 4095);
    int b = (int)(idx >> 20);
    float xc = x[b * Tn + t];
    float xp = (t > 0) ? x[b * Tn + t - 1] : 0.f;
    float h = W[c * 2] * xp + W[c * 2 + 1] * xc + bias[c];
    g_hf[idx] = h;
    g_hbf[idx] = __float2half(h);
}

// ---------------- fp16x2-weights mma.sync GEMM, occ2 + 3-stage overlapped ----------------
// mode 0: conv (16 single-matrix K-chunks: 0-7 f, 8-15 g). mode 1: res (4 chunks).
// grid (Bc*32, 4), 256 threads, 2 CTAs/SM. CTA: 128 t x 64 out-ch.
// 8 warps = wm4 x nw2; per-warp tile 32x32 per matrix.
__global__ void __launch_bounds__(256, 2)
gemm_kernel(int layer, int dil, int mode,
            const float* __restrict__ b0_, const float* __restrict__ b1_) {
    extern __shared__ unsigned char sm[];
    uint32_t smb = smem_u32(sm);
    const int tid = threadIdx.x, wid = tid >> 5, lane = tid & 31;
    const int b = blockIdx.x >> 5, tile = blockIdx.x & 31;
    const int oh2 = blockIdx.y;
    const int t0 = tile * NT;
    const int cg0 = oh2 * 64, oh = oh2 >> 1, slice = oh2 & 1;
    const int nch = mode ? 4 : 16;
    const int wm = wid & 3, nw = wid >> 2;

    const unsigned char* wbase = mode
        ? g_wp2 + ((size_t)(layer * 2 + oh) << 17)
        : g_wp1 + ((size_t)(layer * 2 + oh) << 19);
    const __half* abf = mode ? g_gbf : g_hbf;

    // chunk c -> kc (channel/tap block), mat (0=f/res, 1=g)
    auto load_chunk = [&](int c, int s) {
        uint32_t stb = smb + (uint32_t)s * STAGE_BYTES;
        int kc = mode ? c : (c & 7);
        int mat = mode ? 0 : (c >> 3);
        int toff = (!mode && (kc >> 2) == 0) ? dil : 0;
        int c0 = mode ? kc * 64 : (kc & 3) * 64;
        size_t kcs = mode ? ((size_t)kc << 15) : ((size_t)kc << 16);
        int msb = mode ? 0 : 2 * mat;
        #pragma unroll
        for (int it = 0; it < 8; ++it) {
            int idx = it * 256 + tid;
            if (idx < 1024) {                 // A: 128 rows x 128B single fp16
                int r = idx >> 3, j = idx & 7;
                int t = t0 + r - toff;
                int tc = t < 0 ? 0 : t;
                const char* src = (const char*)(abf + ((size_t)b * Tn + tc) * C + c0) + j * 16;
                cp16(stb + swz((uint32_t)(r * 128 + j * 16)), src, t >= 0 ? 16 : 0);
            } else {                          // B: hi (8KB) then lo (8KB), 64-row slice
                int bi = idx - 1024;          // 0..1023
                int hl = bi >> 9, seg = bi & 511;
                const unsigned char* src = wbase + kcs + (size_t)(msb + hl) * 16384
                                         + (size_t)slice * 8192 + (size_t)seg * 16;
                cp16(stb + 16384 + (uint32_t)bi * 16, src, 16);
            }
        }
        asm volatile("cp.async.commit_group;" ::: "memory");
    };

    load_chunk(0, 0);
    load_chunk(1, 1);

    float acc[2][2][4][4];
    #pragma unroll
    for (int m = 0; m < 2; ++m)
        #pragma unroll
        for (int mt = 0; mt < 2; ++mt)
            #pragma unroll
            for (int nt = 0; nt < 4; ++nt)
                #pragma unroll
                for (int q = 0; q < 4; ++q) acc[m][mt][nt][q] = 0.f;

    const int laneA_r = lane & 15, laneA_j = lane >> 4;
    const int laneB_r = ((lane >> 4) << 3) + (lane & 7), laneB_j = (lane >> 3) & 1;

    for (int i = 0; i < nch; ++i) {
        int s = i % NSTAGE;
        int am = mode ? 0 : (i >> 3);
        if (i + 1 < nch) asm volatile("cp.async.wait_group 1;" ::: "memory");
        else             asm volatile("cp.async.wait_group 0;" ::: "memory");
        __syncthreads();
        if (i + 2 < nch) load_chunk(i + 2, (i + 2) % NSTAGE);  // overlapped with compute

        uint32_t stb = smb + (uint32_t)s * STAGE_BYTES;
        uint32_t bH = stb + 16384, bL = stb + 24576;
        #pragma unroll
        for (int ks = 0; ks < 4; ++ks) {
            uint32_t ah[2][4];
            #pragma unroll
            for (int mt = 0; mt < 2; ++mt) {
                uint32_t off = swz((uint32_t)((wm * 32 + mt * 16 + laneA_r) * 128
                                              + (ks * 2 + laneA_j) * 16));
                LDSM4(ah[mt], stb + off);
            }
            #pragma unroll
            for (int np = 0; np < 2; ++np) {
                uint32_t offB = swz((uint32_t)((nw * 32 + np * 16 + laneB_r) * 128
                                               + (ks * 2 + laneB_j) * 16));
                uint32_t bh[4], bl[4];
                LDSM4(bh, bH + offB);
                LDSM4(bl, bL + offB);
                int n0 = np * 2, n1 = np * 2 + 1;
                #pragma unroll
                for (int mt = 0; mt < 2; ++mt) {
                    MMA(acc[am][mt][n0], ah[mt], bh[0], bh[1]);
                    MMA(acc[am][mt][n1], ah[mt], bh[2], bh[3]);
                    MMA(acc[am][mt][n0], ah[mt], bl[0], bl[1]);
                    MMA(acc[am][mt][n1], ah[mt], bl[2], bl[3]);
                }
            }
        }
    }
    __syncthreads();

    const int rbase = t0 + wm * 32 + (lane >> 2);
    const int cbase = cg0 + nw * 32 + (lane & 3) * 2;

    if (mode == 0) {
        float cs[4][2] = {{0.f,0.f},{0.f,0.f},{0.f,0.f},{0.f,0.f}};
        #pragma unroll
        for (int mt = 0; mt < 2; ++mt)
            #pragma unroll
            for (int nt = 0; nt < 4; ++nt) {
                int c = cbase + nt * 8;
                float bf0 = b0_[c], bf1 = b0_[c + 1];
                float bg0 = b1_[c], bg1 = b1_[c + 1];
                #pragma unroll
                for (int hh = 0; hh < 2; ++hh) {
                    int t = rbase + mt * 16 + hh * 8;
                    float f0 = acc[0][mt][nt][2 * hh]     + bf0;
                    float f1 = acc[0][mt][nt][2 * hh + 1] + bf1;
                    float g0 = acc[1][mt][nt][2 * hh]     + bg0;
                    float g1 = acc[1][mt][nt][2 * hh + 1] + bg1;
                    float v0 = tanhf(f0) / (1.f + expf(-g0));
                    float v1 = tanhf(f1) / (1.f + expf(-g1));
                    size_t base = ((size_t)b * Tn + t) * C + c;
                    *(uint32_t*)(g_gbf + base) = pack2(__float2half(v0), __float2half(v1));
                    cs[nt][0] += v0;
                    cs[nt][1] += v1;
                }
            }
        #pragma unroll
        for (int nt = 0; nt < 4; ++nt)
            #pragma unroll
            for (int q = 0; q < 2; ++q) {
                cs[nt][q] += __shfl_down_sync(0xffffffffu, cs[nt][q], 16);
                cs[nt][q] += __shfl_down_sync(0xffffffffu, cs[nt][q], 8);
                cs[nt][q] += __shfl_down_sync(0xffffffffu, cs[nt][q], 4);
            }
        float* psum = (float*)sm;             // [4 wm][64 cols]
        if (lane < 4) {
            #pragma unroll
            for (int nt = 0; nt < 4; ++nt) {
                int col = nw * 32 + nt * 8 + lane * 2;
                psum[wm * 64 + col]     = cs[nt][0];
                psum[wm * 64 + col + 1] = cs[nt][1];
            }
        }
        __syncthreads();
        if (tid < 64) {
            float s = psum[tid] + psum[64 + tid] + psum[128 + tid] + psum[192 + tid];
            g_part[(((size_t)layer * Bc + b) * 32 + tile) * C + cg0 + tid] = s;
        }
    } else {
        #pragma unroll
        for (int mt = 0; mt < 2; ++mt)
            #pragma unroll
            for (int nt = 0; nt < 4; ++nt) {
                int c = cbase + nt * 8;
                float br0 = b0_[c], br1 = b0_[c + 1];
                #pragma unroll
                for (int hh = 0; hh < 2; ++hh) {
                    int t = rbase + mt * 16 + hh * 8;
                    size_t base = ((size_t)b * Tn + t) * C + c;
                    float2 hv = *(float2*)(g_hf + base);
                    float n0 = acc[0][mt][nt][2 * hh]     + br0 + hv.x;
                    float n1 = acc[0][mt][nt][2 * hh + 1] + br1 + hv.y;
                    *(float2*)(g_hf + base) = make_float2(n0, n1);
                    *(uint32_t*)(g_hbf + base) = pack2(__float2half(n0), __float2half(n1));
                }
            }
    }
}

// ---------------- pooled tail ----------------
__global__ void pool_reduce_kernel() {        // grid NENC*Bc, 256 thr
    int lb = blockIdx.x;
    int c = threadIdx.x;
    const float* p = g_part + ((size_t)lb * 32) * C + c;
    float s = 0.f;
    #pragma unroll 8
    for (int t = 0; t < 32; ++t) s += p[(size_t)t * C];
    g_m[lb * C + c] = s;
}
__global__ void pooled_gemv_kernel(const float* __restrict__ Ws, const float* __restrict__ bs) {
    __shared__ float smm[NENC * C];
    int b = blockIdx.x, cg = blockIdx.y;      // grid (Bc, 32)
    int tid = threadIdx.x, w = tid >> 5, lane = tid & 31;
    for (int i = tid; i < NENC * C; i += 256) {
        int l = i >> 8, k = i & 255;
        smm[i] = g_m[(l * Bc + b) * C + k];
    }
    __syncthreads();
    int c = cg * 8 + w;
    float a = 0.f;
    for (int l = 0; l < NENC; ++l) {
        const float* wrow = Ws + ((size_t)l * C + c) * C;
        const float* mrow = smm + l * C;
        #pragma unroll
        for (int k = lane; k < C; k += 32) a += wrow[k] * mrow[k];
    }
    a += __shfl_down_sync(0xffffffffu, a, 16);
    a += __shfl_down_sync(0xffffffffu, a, 8);
    a += __shfl_down_sync(0xffffffffu, a, 4);
    a += __shfl_down_sync(0xffffffffu, a, 2);
    a += __shfl_down_sync(0xffffffffu, a, 1);
    if (lane == 0) {
        float ab = 0.f;
        for (int l = 0; l < NENC; ++l) ab += bs[l * C + c];
        g_pooled[b * C + c] = a * (1.f / Tn) + ab;
    }
}

// ---------------- mu / logvar / reparameterize ----------------
__global__ void fc_kernel(const float* __restrict__ mub, const float* __restrict__ lvb,
                          const float* __restrict__ eps, float* __restrict__ out) {
    int b = blockIdx.x, l = threadIdx.x;
    const float* p = g_pooled + b * C;
    float m0 = mub[l], v0 = lvb[l];
    for (int c = 0; c < C; ++c) {
        float pv = p[c];
        m0 += g_fmuT[c * LATENT + l] * pv;
        v0 += g_flvT[c * LATENT + l] * pv;
    }
    out[4 + b * LATENT + l] = m0;
    out[4 + Bc * LATENT + b * LATENT + l] = v0;
    g_z[b * LATENT + l] = m0 + eps[b * LATENT + l] * expf(0.5f * v0);
}

// ---------------- decoder ----------------
__global__ void dec_kernel(const float* __restrict__ inb,
                           const float* __restrict__ bf, const float* __restrict__ bg,
                           const float* __restrict__ br,
                           const float* __restrict__ outW, const float* __restrict__ outb,
                           float* __restrict__ out) {
    __shared__ float h2[C], fg[C], red[C];
    int b = blockIdx.x, c = threadIdx.x;
    {
        float s = inb[c];
        const float* zz = g_z + b * LATENT;
        #pragma unroll 4
        for (int l = 0; l < LATENT; ++l) s += g_dinT[l * C + c] * zz[l];
        h2[c] = s;
    }
    __syncthreads();
    for (int i = 0; i < NDEC; ++i) {
        float f = bf[i * C + c], g = bg[i * C + c];
        const float* wf = g_dwfT + (size_t)i * C * C;
        const float* wg = g_dwgT + (size_t)i * C * C;
        #pragma unroll 4
        for (int cc = 0; cc < C; ++cc) {
            float h = h2[cc];
            f += wf[cc * C + c] * h;
            g += wg[cc * C + c] * h;
        }
        fg[c] = tanhf(f) / (1.f + expf(-g));
        __syncthreads();
        float r = br[i * C + c];
        const float* wr = g_dwrT + (size_t)i * C * C;
        #pragma unroll 4
        for (int cc = 0; cc < C; ++cc) r += wr[cc * C + c] * fg[cc];
        h2[c] += r;
        __syncthreads();
    }
    red[c] = outW[c] * h2[c];
    __syncthreads();
    for (int off = 128; off; off >>= 1) {
        if (c < off) red[c] += red[c + off];
        __syncthreads();
    }
    if (c == 0) out[b] = red[0] + outb[0];
}

// ---------------- host ----------------
extern "C" void kernel_launch(void* const* d_in, const int* in_sizes, int n_in,
                              void* d_out, int out_size) {
    const float* x        = (const float*)d_in[0];
    const float* eps      = (const float*)d_in[1];
    const float* enc_in_W = (const float*)d_in[2];
    const float* enc_in_b = (const float*)d_in[3];
    const float* enc_Wf   = (const float*)d_in[4];
    const float* enc_bf   = (const float*)d_in[5];
    const float* enc_Wg   = (const float*)d_in[6];
    const float* enc_bg   = (const float*)d_in[7];
    const float* enc_Wr   = (const float*)d_in[8];
    const float* enc_br   = (const float*)d_in[9];
    const float* enc_Ws   = (const float*)d_in[10];
    const float* enc_bs   = (const float*)d_in[11];
    const float* fc_mu_W  = (const float*)d_in[12];
    const float* fc_mu_b  = (const float*)d_in[13];
    const float* fc_lv_W  = (const float*)d_in[14];
    const float* fc_lv_b  = (const float*)d_in[15];
    const float* dec_in_W = (const float*)d_in[16];
    const float* dec_in_b = (const float*)d_in[17];
    const float* dec_Wf   = (const float*)d_in[18];
    const float* dec_bf   = (const float*)d_in[19];
    const float* dec_Wg   = (const float*)d_in[20];
    const float* dec_bg   = (const float*)d_in[21];
    const float* dec_Wr   = (const float*)d_in[22];
    const float* dec_br   = (const float*)d_in[23];
    const float* out_W    = (const float*)d_in[24];
    const float* out_b    = (const float*)d_in[25];
    float* out = (float*)d_out;

    cudaFuncSetAttribute(gemm_kernel, cudaFuncAttributeMaxDynamicSharedMemorySize, SMEM_TOTAL);

    prep1_kernel<<<10240, 256>>>(enc_Wf, enc_Wg);
    prep2_kernel<<<5120, 256>>>(enc_Wr);
    prep3_kernel<<<2560, 256>>>(dec_Wf, dec_Wg, dec_Wr, dec_in_W, fc_mu_W, fc_lv_W);
    enc_in_kernel<<<(Bc * Tn * C) / 256, 256>>>(x, enc_in_W, enc_in_b);

    for (int i = 0; i < NENC; ++i) {
        int dil = 1 << (i % 10);
        gemm_kernel<<<dim3(Bc * 32, 4), 256, SMEM_TOTAL>>>(i, dil, 0,
                                                           enc_bf + i * C, enc_bg + i * C);
        gemm_kernel<<<dim3(Bc * 32, 4), 256, SMEM_TOTAL>>>(i, 0, 1,
                                                           enc_br + i * C, (const float*)0);
    }

    pool_reduce_kernel<<<NENC * Bc, 256>>>();
    pooled_gemv_kernel<<<dim3(Bc, 32), 256>>>(enc_Ws, enc_bs);
    fc_kernel<<<Bc, LATENT>>>(fc_mu_b, fc_lv_b, eps, out);
    dec_kernel<<<Bc, C>>>(dec_in_b, dec_bf, dec_bg, dec_br, out_W, out_b, out);
}

// round 17
// speedup vs baseline: 1.4861x; 1.4861x over previous
#include <cuda_runtime.h>
#include <cuda_fp16.h>
#include <math.h>
#include <stdint.h>

#define Bc 4
#define C 256
#define Tn 4096
#define LATENT 128
#define NENC 40
#define NDEC 10
#define NT 128

#define STAGE_BYTES 49152      // A 16K + B up to 32K
#define NSTAGE 2
#define SMEM_TOTAL (NSTAGE * STAGE_BYTES)

// ---------------- device scratch ----------------
__device__ __align__(16) unsigned char g_wp1[(size_t)NENC * 2 * 8 * 4 * 16384]; // 40MB
__device__ __align__(16) unsigned char g_wp2[(size_t)NENC * 2 * 4 * 2 * 16384]; // 10MB
__device__ __align__(16) float  g_hf  [(size_t)Bc * Tn * C];
__device__ __align__(16) __half g_hbf [(size_t)Bc * Tn * C];
__device__ __align__(16) __half g_gbf [(size_t)Bc * Tn * C];
__device__ float g_part[(size_t)NENC * Bc * 32 * C];
__device__ float g_m[NENC * Bc * C];
__device__ float g_pooled[Bc * C];
__device__ float g_z[Bc * LATENT];
__device__ float g_dwfT[NDEC * C * C], g_dwgT[NDEC * C * C], g_dwrT[NDEC * C * C];
__device__ float g_dinT[LATENT * C];
__device__ float g_fmuT[C * LATENT], g_flvT[C * LATENT];

// ---------------- helpers ----------------
__device__ __forceinline__ uint32_t smem_u32(const void* p) {
    uint32_t a;
    asm("{ .reg .u64 t; cvta.to.shared.u64 t, %1; cvt.u32.u64 %0, t; }" : "=r"(a) : "l"(p));
    return a;
}
__device__ __forceinline__ uint32_t swz(uint32_t off) { return off ^ ((off >> 3) & 0x70); }
__device__ __forceinline__ void cp16(uint32_t dst, const void* src, int sz) {
    asm volatile("cp.async.cg.shared.global [%0], [%1], 16, %2;"
                 :: "r"(dst), "l"(src), "r"(sz) : "memory");
}
#define LDSM4(r, addr) \
    asm volatile("ldmatrix.sync.aligned.m8n8.x4.shared.b16 {%0,%1,%2,%3}, [%4];" \
                 : "=r"((r)[0]), "=r"((r)[1]), "=r"((r)[2]), "=r"((r)[3]) : "r"(addr))
#define MMA(c, a, b0r, b1r) \
    asm volatile("mma.sync.aligned.m16n8k16.row.col.f32.f16.f16.f32 " \
                 "{%0,%1,%2,%3}, {%4,%5,%6,%7}, {%8,%9}, {%0,%1,%2,%3};" \
                 : "+f"((c)[0]), "+f"((c)[1]), "+f"((c)[2]), "+f"((c)[3]) \
                 : "r"((a)[0]), "r"((a)[1]), "r"((a)[2]), "r"((a)[3]), "r"(b0r), "r"(b1r))

__device__ __forceinline__ void split2(float v, __half& h, __half& l) {
    h = __float2half(v);
    l = __float2half(v - __half2float(h));
}
__device__ __forceinline__ uint32_t pack2(__half a, __half b) {
    return (uint32_t)__half_as_ushort(a) | ((uint32_t)__half_as_ushort(b) << 16);
}

// ---------------- weight pre-pack: fp16 hi/lo (layouts identical to R12/R14) ----------------
__global__ void prep1_kernel(const float* __restrict__ Wf, const float* __restrict__ Wg) {
    size_t idx = (size_t)blockIdx.x * 256 + threadIdx.x;
    int j2 = idx & 31;
    int r  = (idx >> 5) & 127;
    int kc = (idx >> 12) & 7;
    int oh = (idx >> 15) & 1;
    int l  = (int)(idx >> 16);
    int o = oh * 128 + r;
    int tap = kc >> 2;
    int c = (kc & 3) * 64 + j2 * 2;
    uint32_t boff = swz((uint32_t)(r * 128 + j2 * 4));
    unsigned char* base = g_wp1 + ((((size_t)(l * 2 + oh) * 8 + kc) * 4) << 14) + boff;
    const float* pf = Wf + (((size_t)l * C + o) * C + c) * 2 + tap;
    const float* pg = Wg + (((size_t)l * C + o) * C + c) * 2 + tap;
    __half h0, l0, h1, l1;
    split2(pf[0], h0, l0); split2(pf[2], h1, l1);
    *(uint32_t*)(base)             = pack2(h0, h1);
    *(uint32_t*)(base + 16384)     = pack2(l0, l1);
    split2(pg[0], h0, l0); split2(pg[2], h1, l1);
    *(uint32_t*)(base + 2 * 16384) = pack2(h0, h1);
    *(uint32_t*)(base + 3 * 16384) = pack2(l0, l1);
}
__global__ void prep2_kernel(const float* __restrict__ Wr) {
    size_t idx = (size_t)blockIdx.x * 256 + threadIdx.x;
    int j2 = idx & 31;
    int r  = (idx >> 5) & 127;
    int kc = (idx >> 12) & 3;
    int oh = (idx >> 14) & 1;
    int l  = (int)(idx >> 15);
    int o = oh * 128 + r;
    int c = kc * 64 + j2 * 2;
    uint32_t boff = swz((uint32_t)(r * 128 + j2 * 4));
    unsigned char* base = g_wp2 + ((((size_t)(l * 2 + oh) * 4 + kc) * 2) << 14) + boff;
    const float* pr = Wr + ((size_t)l * C + o) * C + c;
    __half h0, l0, h1, l1;
    split2(pr[0], h0, l0); split2(pr[1], h1, l1);
    *(uint32_t*)(base)         = pack2(h0, h1);
    *(uint32_t*)(base + 16384) = pack2(l0, l1);
}
__global__ void prep3_kernel(const float* __restrict__ dWf, const float* __restrict__ dWg,
                             const float* __restrict__ dWr, const float* __restrict__ dinW,
                             const float* __restrict__ muW, const float* __restrict__ lvW) {
    int idx = blockIdx.x * 256 + threadIdx.x;
    if (idx < NDEC * C * C) {
        int o = idx & 255, cc = (idx >> 8) & 255, l = idx >> 16;
        g_dwfT[idx] = dWf[(((size_t)l * C + o) * C + cc) * 2 + 1];
        g_dwgT[idx] = dWg[(((size_t)l * C + o) * C + cc) * 2 + 1];
        g_dwrT[idx] = dWr[((size_t)l * C + o) * C + cc];
    }
    if (idx < LATENT * C) {
        int o = idx & 255, l = idx >> 8;
        g_dinT[idx] = dinW[o * LATENT + l];
    }
    if (idx < C * LATENT) {
        int l = idx & 127, c = idx >> 7;
        g_fmuT[idx] = muW[l * C + c];
        g_flvT[idx] = lvW[l * C + c];
    }
}

// ---------------- encoder input conv ----------------
__global__ void enc_in_kernel(const float* __restrict__ x,
                              const float* __restrict__ W,
                              const float* __restrict__ bias) {
    size_t idx = (size_t)blockIdx.x * 256 + threadIdx.x;
    int c = idx & 255;
    int t = (int)((idx >> 8) & 4095);
    int b = (int)(idx >> 20);
    float xc = x[b * Tn + t];
    float xp = (t > 0) ? x[b * Tn + t - 1] : 0.f;
    float h = W[c * 2] * xp + W[c * 2 + 1] * xc + bias[c];
    g_hf[idx] = h;
    g_hbf[idx] = __float2half(h);
}

// ---------------- fp16x2-weights mma.sync GEMM kernel, occ2, wm2 x nw4 ----------------
// mode 0: conv f/g (8 K-chunks, dilation). mode 1: res 1x1 (4 K-chunks).
// grid (Bc*32, 4), 256 threads, 2 CTAs/SM. CTA: 128 t x 64 out-ch.
// 8 warps = wm2 (64 rows) x nw4 (16 cols per matrix): B dup x2, A dup x4.
__global__ void __launch_bounds__(256, 2)
gemm_kernel(int layer, int dil, int mode,
            const float* __restrict__ b0_, const float* __restrict__ b1_) {
    extern __shared__ unsigned char sm[];
    uint32_t smb = smem_u32(sm);
    const int tid = threadIdx.x, wid = tid >> 5, lane = tid & 31;
    const int b = blockIdx.x >> 5, tile = blockIdx.x & 31;
    const int oh2 = blockIdx.y;
    const int t0 = tile * NT;
    const int cg0 = oh2 * 64, oh = oh2 >> 1, slice = oh2 & 1;
    const int nch = mode ? 4 : 8;
    const int nB = mode ? 1024 : 2048;
    const int nmat = mode ? 1 : 2;
    const int wm = wid & 1, nw = wid >> 1;

    const unsigned char* wbase = mode
        ? g_wp2 + ((size_t)(layer * 2 + oh) << 17)
        : g_wp1 + ((size_t)(layer * 2 + oh) << 19);
    const __half* abf = mode ? g_gbf : g_hbf;

    auto load_chunk = [&](int kc, int s) {
        uint32_t stb = smb + (uint32_t)s * STAGE_BYTES;
        int toff = (!mode && (kc >> 2) == 0) ? dil : 0;
        int c0 = mode ? kc * 64 : (kc & 3) * 64;
        size_t kcs = mode ? ((size_t)kc << 15) : ((size_t)kc << 16);
        int nseg = 1024 + nB;
        #pragma unroll
        for (int it = 0; it < 12; ++it) {
            int idx = it * 256 + tid;
            if (idx < 1024) {                 // A: 128 rows x 128B single fp16
                int r = idx >> 3, j = idx & 7;
                int t = t0 + r - toff;
                int tc = t < 0 ? 0 : t;
                const char* src = (const char*)(abf + ((size_t)b * Tn + tc) * C + c0) + j * 16;
                cp16(stb + swz((uint32_t)(r * 128 + j * 16)), src, t >= 0 ? 16 : 0);
            } else if (idx < nseg) {          // B weights hi/lo, pre-swizzled, linear
                int bi = idx - 1024;
                int ms = bi >> 9, seg = bi & 511;
                const unsigned char* src = wbase + kcs + (size_t)ms * 16384
                                         + (size_t)slice * 8192 + (size_t)seg * 16;
                cp16(stb + 16384 + (uint32_t)bi * 16, src, 16);
            }
        }
        asm volatile("cp.async.commit_group;" ::: "memory");
    };

    load_chunk(0, 0);
    load_chunk(1, 1);

    float acc[2][4][2][4];     // [mat][mt][nt][quad]
    #pragma unroll
    for (int m = 0; m < 2; ++m)
        #pragma unroll
        for (int mt = 0; mt < 4; ++mt)
            #pragma unroll
            for (int nt = 0; nt < 2; ++nt)
                #pragma unroll
                for (int q = 0; q < 4; ++q) acc[m][mt][nt][q] = 0.f;

    const int laneA_r = lane & 15, laneA_j = lane >> 4;
    const int laneB_r = ((lane >> 4) << 3) + (lane & 7), laneB_j = (lane >> 3) & 1;

    for (int i = 0; i < nch; ++i) {
        int s = i & 1;
        if (i + 1 < nch) asm volatile("cp.async.wait_group 1;" ::: "memory");
        else             asm volatile("cp.async.wait_group 0;" ::: "memory");
        __syncthreads();

        uint32_t stb = smb + (uint32_t)s * STAGE_BYTES;
        #pragma unroll
        for (int ks = 0; ks < 4; ++ks) {
            uint32_t ah[4][4];
            #pragma unroll
            for (int mt = 0; mt < 4; ++mt) {
                uint32_t off = swz((uint32_t)((wm * 64 + mt * 16 + laneA_r) * 128
                                              + (ks * 2 + laneA_j) * 16));
                LDSM4(ah[mt], stb + off);
            }
            uint32_t offB = swz((uint32_t)((nw * 16 + laneB_r) * 128
                                           + (ks * 2 + laneB_j) * 16));
            #pragma unroll
            for (int m = 0; m < 2; ++m) {
                if (m >= nmat) break;
                uint32_t bB = stb + 16384 + (uint32_t)m * 16384;
                uint32_t bh[4], bl[4];
                LDSM4(bh, bB + offB);
                LDSM4(bl, bB + 8192 + offB);
                #pragma unroll
                for (int mt = 0; mt < 4; ++mt) {
                    MMA(acc[m][mt][0], ah[mt], bh[0], bh[1]);
                    MMA(acc[m][mt][1], ah[mt], bh[2], bh[3]);
                    MMA(acc[m][mt][0], ah[mt], bl[0], bl[1]);
                    MMA(acc[m][mt][1], ah[mt], bl[2], bl[3]);
                }
            }
        }
        __syncthreads();                      // all reads of stage s done
        if (i + 2 < nch) load_chunk(i + 2, s);
    }

    const int rbase = t0 + wm * 64 + (lane >> 2);
    const int cbase = cg0 + nw * 16 + (lane & 3) * 2;

    if (mode == 0) {
        float cs[2][2] = {{0.f, 0.f}, {0.f, 0.f}};
        #pragma unroll
        for (int nt = 0; nt < 2; ++nt) {
            int c = cbase + nt * 8;
            float bf0 = b0_[c], bf1 = b0_[c + 1];
            float bg0 = b1_[c], bg1 = b1_[c + 1];
            #pragma unroll
            for (int mt = 0; mt < 4; ++mt)
                #pragma unroll
                for (int hh = 0; hh < 2; ++hh) {
                    int t = rbase + mt * 16 + hh * 8;
                    float f0 = acc[0][mt][nt][2 * hh]     + bf0;
                    float f1 = acc[0][mt][nt][2 * hh + 1] + bf1;
                    float g0 = acc[1][mt][nt][2 * hh]     + bg0;
                    float g1 = acc[1][mt][nt][2 * hh + 1] + bg1;
                    float v0 = tanhf(f0) / (1.f + expf(-g0));
                    float v1 = tanhf(f1) / (1.f + expf(-g1));
                    size_t base = ((size_t)b * Tn + t) * C + c;
                    *(uint32_t*)(g_gbf + base) = pack2(__float2half(v0), __float2half(v1));
                    cs[nt][0] += v0;
                    cs[nt][1] += v1;
                }
        }
        #pragma unroll
        for (int nt = 0; nt < 2; ++nt)
            #pragma unroll
            for (int q = 0; q < 2; ++q) {
                cs[nt][q] += __shfl_down_sync(0xffffffffu, cs[nt][q], 16);
                cs[nt][q] += __shfl_down_sync(0xffffffffu, cs[nt][q], 8);
                cs[nt][q] += __shfl_down_sync(0xffffffffu, cs[nt][q], 4);
            }
        float* psum = (float*)sm;             // [2 wm][64 cols]
        if (lane < 4) {
            #pragma unroll
            for (int nt = 0; nt < 2; ++nt) {
                int col = nw * 16 + nt * 8 + lane * 2;
                psum[wm * 64 + col]     = cs[nt][0];
                psum[wm * 64 + col + 1] = cs[nt][1];
            }
        }
        __syncthreads();
        if (tid < 64) {
            float s = psum[tid] + psum[64 + tid];
            g_part[(((size_t)layer * Bc + b) * 32 + tile) * C + cg0 + tid] = s;
        }
    } else {
        #pragma unroll
        for (int nt = 0; nt < 2; ++nt) {
            int c = cbase + nt * 8;
            float br0 = b0_[c], br1 = b0_[c + 1];
            #pragma unroll
            for (int mt = 0; mt < 4; ++mt)
                #pragma unroll
                for (int hh = 0; hh < 2; ++hh) {
                    int t = rbase + mt * 16 + hh * 8;
                    size_t base = ((size_t)b * Tn + t) * C + c;
                    float2 hv = *(float2*)(g_hf + base);
                    float n0 = acc[0][mt][nt][2 * hh]     + br0 + hv.x;
                    float n1 = acc[0][mt][nt][2 * hh + 1] + br1 + hv.y;
                    *(float2*)(g_hf + base) = make_float2(n0, n1);
                    *(uint32_t*)(g_hbf + base) = pack2(__float2half(n0), __float2half(n1));
                }
        }
    }
}

// ---------------- pooled tail ----------------
__global__ void pool_reduce_kernel() {        // grid NENC*Bc, 256 thr
    int lb = blockIdx.x;
    int c = threadIdx.x;
    const float* p = g_part + ((size_t)lb * 32) * C + c;
    float s = 0.f;
    #pragma unroll 8
    for (int t = 0; t < 32; ++t) s += p[(size_t)t * C];
    g_m[lb * C + c] = s;
}
__global__ void pooled_gemv_kernel(const float* __restrict__ Ws, const float* __restrict__ bs) {
    __shared__ float smm[NENC * C];
    int b = blockIdx.x, cg = blockIdx.y;      // grid (Bc, 32)
    int tid = threadIdx.x, w = tid >> 5, lane = tid & 31;
    for (int i = tid; i < NENC * C; i += 256) {
        int l = i >> 8, k = i & 255;
        smm[i] = g_m[(l * Bc + b) * C + k];
    }
    __syncthreads();
    int c = cg * 8 + w;
    float a = 0.f;
    for (int l = 0; l < NENC; ++l) {
        const float* wrow = Ws + ((size_t)l * C + c) * C;
        const float* mrow = smm + l * C;
        #pragma unroll
        for (int k = lane; k < C; k += 32) a += wrow[k] * mrow[k];
    }
    a += __shfl_down_sync(0xffffffffu, a, 16);
    a += __shfl_down_sync(0xffffffffu, a, 8);
    a += __shfl_down_sync(0xffffffffu, a, 4);
    a += __shfl_down_sync(0xffffffffu, a, 2);
    a += __shfl_down_sync(0xffffffffu, a, 1);
    if (lane == 0) {
        float ab = 0.f;
        for (int l = 0; l < NENC; ++l) ab += bs[l * C + c];
        g_pooled[b * C + c] = a * (1.f / Tn) + ab;
    }
}

// ---------------- mu / logvar / reparameterize ----------------
__global__ void fc_kernel(const float* __restrict__ mub, const float* __restrict__ lvb,
                          const float* __restrict__ eps, float* __restrict__ out) {
    int b = blockIdx.x, l = threadIdx.x;
    const float* p = g_pooled + b * C;
    float m0 = mub[l], v0 = lvb[l];
    for (int c = 0; c < C; ++c) {
        float pv = p[c];
        m0 += g_fmuT[c * LATENT + l] * pv;
        v0 += g_flvT[c * LATENT + l] * pv;
    }
    out[4 + b * LATENT + l] = m0;
    out[4 + Bc * LATENT + b * LATENT + l] = v0;
    g_z[b * LATENT + l] = m0 + eps[b * LATENT + l] * expf(0.5f * v0);
}

// ---------------- decoder ----------------
__global__ void dec_kernel(const float* __restrict__ inb,
                           const float* __restrict__ bf, const float* __restrict__ bg,
                           const float* __restrict__ br,
                           const float* __restrict__ outW, const float* __restrict__ outb,
                           float* __restrict__ out) {
    __shared__ float h2[C], fg[C], red[C];
    int b = blockIdx.x, c = threadIdx.x;
    {
        float s = inb[c];
        const float* zz = g_z + b * LATENT;
        #pragma unroll 4
        for (int l = 0; l < LATENT; ++l) s += g_dinT[l * C + c] * zz[l];
        h2[c] = s;
    }
    __syncthreads();
    for (int i = 0; i < NDEC; ++i) {
        float f = bf[i * C + c], g = bg[i * C + c];
        const float* wf = g_dwfT + (size_t)i * C * C;
        const float* wg = g_dwgT + (size_t)i * C * C;
        #pragma unroll 4
        for (int cc = 0; cc < C; ++cc) {
            float h = h2[cc];
            f += wf[cc * C + c] * h;
            g += wg[cc * C + c] * h;
        }
        fg[c] = tanhf(f) / (1.f + expf(-g));
        __syncthreads();
        float r = br[i * C + c];
        const float* wr = g_dwrT + (size_t)i * C * C;
        #pragma unroll 4
        for (int cc = 0; cc < C; ++cc) r += wr[cc * C + c] * fg[cc];
        h2[c] += r;
        __syncthreads();
    }
    red[c] = outW[c] * h2[c];
    __syncthreads();
    for (int off = 128; off; off >>= 1) {
        if (c < off) red[c] += red[c + off];
        __syncthreads();
    }
    if (c == 0) out[b] = red[0] + outb[0];
}

// ---------------- host ----------------
extern "C" void kernel_launch(void* const* d_in, const int* in_sizes, int n_in,
                              void* d_out, int out_size) {
    const float* x        = (const float*)d_in[0];
    const float* eps      = (const float*)d_in[1];
    const float* enc_in_W = (const float*)d_in[2];
    const float* enc_in_b = (const float*)d_in[3];
    const float* enc_Wf   = (const float*)d_in[4];
    const float* enc_bf   = (const float*)d_in[5];
    const float* enc_Wg   = (const float*)d_in[6];
    const float* enc_bg   = (const float*)d_in[7];
    const float* enc_Wr   = (const float*)d_in[8];
    const float* enc_br   = (const float*)d_in[9];
    const float* enc_Ws   = (const float*)d_in[10];
    const float* enc_bs   = (const float*)d_in[11];
    const float* fc_mu_W  = (const float*)d_in[12];
    const float* fc_mu_b  = (const float*)d_in[13];
    const float* fc_lv_W  = (const float*)d_in[14];
    const float* fc_lv_b  = (const float*)d_in[15];
    const float* dec_in_W = (const float*)d_in[16];
    const float* dec_in_b = (const float*)d_in[17];
    const float* dec_Wf   = (const float*)d_in[18];
    const float* dec_bf   = (const float*)d_in[19];
    const float* dec_Wg   = (const float*)d_in[20];
    const float* dec_bg   = (const float*)d_in[21];
    const float* dec_Wr   = (const float*)d_in[22];
    const float* dec_br   = (const float*)d_in[23];
    const float* out_W    = (const float*)d_in[24];
    const float* out_b    = (const float*)d_in[25];
    float* out = (float*)d_out;

    cudaFuncSetAttribute(gemm_kernel, cudaFuncAttributeMaxDynamicSharedMemorySize, SMEM_TOTAL);

    prep1_kernel<<<10240, 256>>>(enc_Wf, enc_Wg);
    prep2_kernel<<<5120, 256>>>(enc_Wr);
    prep3_kernel<<<2560, 256>>>(dec_Wf, dec_Wg, dec_Wr, dec_in_W, fc_mu_W, fc_lv_W);
    enc_in_kernel<<<(Bc * Tn * C) / 256, 256>>>(x, enc_in_W, enc_in_b);

    for (int i = 0; i < NENC; ++i) {
        int dil = 1 << (i % 10);
        gemm_kernel<<<dim3(Bc * 32, 4), 256, SMEM_TOTAL>>>(i, dil, 0,
                                                           enc_bf + i * C, enc_bg + i * C);
        gemm_kernel<<<dim3(Bc * 32, 4), 256, SMEM_TOTAL>>>(i, 0, 1,
                                                           enc_br + i * C, (const float*)0);
    }

    pool_reduce_kernel<<<NENC * Bc, 256>>>();
    pooled_gemv_kernel<<<dim3(Bc, 32), 256>>>(enc_Ws, enc_bs);
    fc_kernel<<<Bc, LATENT>>>(fc_mu_b, fc_lv_b, eps, out);
    dec_kernel<<<Bc, C>>>(dec_in_b, dec_bf, dec_bg, dec_br, out_W, out_b, out);
}